// round 13
// baseline (speedup 1.0000x reference)
#include <cuda_runtime.h>
#include <cstdint>

#define Zdim 41
#define Ydim 1024
#define Xdim 1024
#define NVOX (Zdim * Ydim * Xdim)      // 42,991,616
#define NWORDS (NVOX / 32)             // 1,343,488
#define C_IN 32
#define C_OUT 64
#define KVOL 27
#define KCENTER 13
#define MAXN 300000
#define TILE 64

// Dense index grid: validity gated by g_bitmap (wiped each launch); the grid
// itself is never cleared, so stale entries are never read.
__device__ int      g_grid[NVOX];
__device__ unsigned g_bitmap[NWORDS];
__device__ int      g_npairs;
__device__ int2     g_pairs[MAXN * 8];

// Side stream + fork/join events, created once at static init (host-side
// driver resources; no device allocations in kernel_launch).
static cudaStream_t g_s1;
static cudaEvent_t  g_ev_fork, g_ev_join;
namespace {
struct StreamInit {
    StreamInit() {
        cudaStreamCreateWithFlags(&g_s1, cudaStreamNonBlocking);
        cudaEventCreateWithFlags(&g_ev_fork, cudaEventDisableTiming);
        cudaEventCreateWithFlags(&g_ev_join, cudaEventDisableTiming);
    }
};
StreamInit g_stream_init;
}

__global__ void clear_bitmap_kernel() {
    int i = blockIdx.x * blockDim.x + threadIdx.x;
    if (i == 0) g_npairs = 0;
    if (i * 4 < NWORDS) ((uint4*)g_bitmap)[i] = make_uint4(0, 0, 0, 0);
}

__global__ void scatter_kernel(const int* __restrict__ idx, int n) {
    int i = blockIdx.x * blockDim.x + threadIdx.x;
    if (i >= n) return;
    int4 v = ((const int4*)idx)[i];
    unsigned lin = (unsigned)v.y * (Ydim * Xdim) + (unsigned)v.z * Xdim + (unsigned)v.w;
    g_grid[lin] = i;
    atomicOr(&g_bitmap[lin >> 5], 1u << (lin & 31));
}

// Symmetric probing, ONE THREAD PER POINT: all 5 group bitmap words issued
// as independent LDGs first (MLP=5), then tested. Only k<13 probed; each
// hit emits the pair AND its mirror. Row base is 32-aligned (X=1024), so
// each group's dx-triplet shares one word except at x&31 in {0,31}.
__global__ void probe_kernel(const int* __restrict__ idx, int n) {
    int i = blockIdx.x * blockDim.x + threadIdx.x;
    if (i >= n) return;
    int4 v = ((const int4*)idx)[i];
    int x = v.w;

    // group -> (dz,dy): 0:(-1,-1) 1:(-1,0) 2:(-1,1) 3:(0,-1) 4:(0,0,dx=-1 only)
    unsigned rowbase[5];
    unsigned words[5];
    bool     okg[5];
    #pragma unroll
    for (int g = 0; g < 5; ++g) {
        int dz = (g < 3) ? -1 : 0;
        int dy = (g < 3) ? (g - 1) : (g - 4);
        int nz = v.y + dz;
        int ny = v.z + dy;
        bool ok = ((unsigned)nz < Zdim) & ((unsigned)ny < Ydim);
        okg[g] = ok;
        unsigned rb = ((unsigned)nz * Ydim + (unsigned)ny) * Xdim;
        rowbase[g] = rb;
        // independent loads, all in flight together (clamped when oob)
        words[g] = ok ? g_bitmap[(rb + (unsigned)x) >> 5] : 0u;
    }

    #pragma unroll
    for (int g = 0; g < 5; ++g) {
        if (!okg[g]) continue;
        int dz = (g < 3) ? -1 : 0;
        int dy = (g < 3) ? (g - 1) : (g - 4);
        int kbase = (dz + 1) * 9 + (dy + 1) * 3;
        int dxhi = (g == 4) ? -1 : 1;
        unsigned base_word_idx = (rowbase[g] + (unsigned)x) >> 5;

        #pragma unroll
        for (int dx = -1; dx <= 1; ++dx) {
            if (dx > dxhi) break;
            int nx = x + dx;
            if ((unsigned)nx >= Xdim) continue;
            unsigned lin = rowbase[g] + (unsigned)nx;
            unsigned word = ((lin >> 5) == base_word_idx) ? words[g]
                                                         : g_bitmap[lin >> 5];
            if ((word >> (lin & 31)) & 1u) {
                int nb = g_grid[lin];                 // rare
                int k = kbase + dx + 1;
                int pos = atomicAdd(&g_npairs, 2);
                g_pairs[pos]     = make_int2((i  << 5) | k,        nb);
                g_pairs[pos + 1] = make_int2((nb << 5) | (26 - k), i);
            }
        }
    }
}

__device__ __forceinline__ void fma2(unsigned long long& acc, float f,
                                     unsigned long long wv) {
    unsigned long long fv2;
    asm("mov.b64 %0, {%1, %1};" : "=l"(fv2) : "f"(f));
    asm("fma.rn.f32x2 %0, %1, %2, %3;" : "=l"(acc) : "l"(fv2), "l"(wv), "l"(acc));
}

// Center matvec, NON-PERSISTENT: one 64-point tile per block (grid=ntiles).
// Blocks retire every ~1.5us so chain-kernel blocks can interleave into the
// freed register file (real overlap with the scatter/probe branch).
// Lane owns couts (2*lane, 2*lane+1): packed u64 weights in registers,
// broadcast LDS.128 features, one STG.64 per point.
__global__ void __launch_bounds__(256) center_kernel(
    const float* __restrict__ feat, const float* __restrict__ w,
    float* __restrict__ out, int n)
{
    __shared__ float4 sf[TILE * (C_IN / 4)];   // 8 KB

    int tid   = threadIdx.x;
    int lane  = tid & 31;
    int wslot = tid >> 5;
    int t     = blockIdx.x;

    // Per-lane weights (L1/L2-hot after first blocks touch them).
    const unsigned long long* w13v =
        (const unsigned long long*)(w + KCENTER * C_IN * C_OUT);
    unsigned long long wreg[C_IN];
    #pragma unroll
    for (int c = 0; c < C_IN; ++c)
        wreg[c] = w13v[c * 32 + lane];

    // Stage this block's tile (coalesced LDG.128).
    const float4* featv = (const float4*)feat;
    long maxf4 = (long)n * (C_IN / 4) - 1;
    long base = (long)t * (TILE * C_IN / 4);
    long i0 = base + tid;       if (i0 > maxf4) i0 = maxf4;
    long i1 = base + tid + 256; if (i1 > maxf4) i1 = maxf4;
    sf[tid]       = featv[i0];
    sf[tid + 256] = featv[i1];
    __syncthreads();

    int p0 = wslot * 8;
    #pragma unroll
    for (int pp = 0; pp < 8; ++pp) {
        int i = t * TILE + p0 + pp;
        if (i >= n) break;
        const float4* frow = &sf[(p0 + pp) * (C_IN / 4)];
        unsigned long long acc0, acc1, acc2, acc3;
        asm("mov.b64 %0, {%1, %1};" : "=l"(acc0) : "f"(0.0f));
        asm("mov.b64 %0, {%1, %1};" : "=l"(acc1) : "f"(0.0f));
        asm("mov.b64 %0, {%1, %1};" : "=l"(acc2) : "f"(0.0f));
        asm("mov.b64 %0, {%1, %1};" : "=l"(acc3) : "f"(0.0f));
        #pragma unroll
        for (int c4 = 0; c4 < C_IN / 4; ++c4) {
            float4 fv = frow[c4];                // broadcast LDS.128
            fma2(acc0, fv.x, wreg[c4 * 4 + 0]);
            fma2(acc1, fv.y, wreg[c4 * 4 + 1]);
            fma2(acc2, fv.z, wreg[c4 * 4 + 2]);
            fma2(acc3, fv.w, wreg[c4 * 4 + 3]);
        }
        unsigned long long s01, s23, s;
        asm("add.rn.f32x2 %0, %1, %2;" : "=l"(s01) : "l"(acc0), "l"(acc1));
        asm("add.rn.f32x2 %0, %1, %2;" : "=l"(s23) : "l"(acc2), "l"(acc3));
        asm("add.rn.f32x2 %0, %1, %2;" : "=l"(s)   : "l"(s01),  "l"(s23));
        ((unsigned long long*)out)[(size_t)i * 32 + lane] = s;   // STG.64
    }
}

// Rare neighbor contributions. 2 pairs/warp-iteration; ALL 16 feature
// float4 loads preloaded into registers before any FMA (MLP=16).
// Weights packed u64 (lane owns couts 2lane/2lane+1), hot in L1/L2.
__global__ void __launch_bounds__(128, 4) pairs_kernel(
    const float* __restrict__ feat,
    const float* __restrict__ w,
    float* __restrict__ out)
{
    int lane   = threadIdx.x & 31;
    int warp_g = (blockIdx.x * blockDim.x + threadIdx.x) >> 5;
    int nwarps = (gridDim.x * blockDim.x) >> 5;
    int np = g_npairs;

    for (int p = warp_g * 2; p < np; p += nwarps * 2) {
        int4 pq = ((const int4*)g_pairs)[p >> 1];
        bool has1 = (p + 1) < np;

        const float4* f0v = (const float4*)(feat + (size_t)pq.y * C_IN);
        const float4* f1v = (const float4*)(feat + (size_t)(has1 ? pq.w : pq.y) * C_IN);

        float4 f0[8], f1[8];
        #pragma unroll
        for (int c4 = 0; c4 < 8; ++c4) f0[c4] = f0v[c4];
        #pragma unroll
        for (int c4 = 0; c4 < 8; ++c4) f1[c4] = f1v[c4];

        const unsigned long long* wk0 =
            (const unsigned long long*)(w + (size_t)(pq.x & 31) * C_IN * C_OUT);
        const unsigned long long* wk1 =
            (const unsigned long long*)(w + (size_t)(pq.z & 31) * C_IN * C_OUT);

        unsigned long long a0, a1, b0, b1;
        asm("mov.b64 %0, {%1, %1};" : "=l"(a0) : "f"(0.0f));
        asm("mov.b64 %0, {%1, %1};" : "=l"(a1) : "f"(0.0f));
        asm("mov.b64 %0, {%1, %1};" : "=l"(b0) : "f"(0.0f));
        asm("mov.b64 %0, {%1, %1};" : "=l"(b1) : "f"(0.0f));

        #pragma unroll
        for (int c4 = 0; c4 < 8; ++c4) {
            fma2(a0, f0[c4].x, wk0[(c4 * 4 + 0) * 32 + lane]);
            fma2(a1, f0[c4].y, wk0[(c4 * 4 + 1) * 32 + lane]);
            fma2(a0, f0[c4].z, wk0[(c4 * 4 + 2) * 32 + lane]);
            fma2(a1, f0[c4].w, wk0[(c4 * 4 + 3) * 32 + lane]);
            fma2(b0, f1[c4].x, wk1[(c4 * 4 + 0) * 32 + lane]);
            fma2(b1, f1[c4].y, wk1[(c4 * 4 + 1) * 32 + lane]);
            fma2(b0, f1[c4].z, wk1[(c4 * 4 + 2) * 32 + lane]);
            fma2(b1, f1[c4].w, wk1[(c4 * 4 + 3) * 32 + lane]);
        }

        unsigned long long sa, sb;
        asm("add.rn.f32x2 %0, %1, %2;" : "=l"(sa) : "l"(a0), "l"(a1));
        asm("add.rn.f32x2 %0, %1, %2;" : "=l"(sb) : "l"(b0), "l"(b1));
        float sa0, sa1, sb0, sb1;
        asm("mov.b64 {%0, %1}, %2;" : "=f"(sa0), "=f"(sa1) : "l"(sa));
        asm("mov.b64 {%0, %1}, %2;" : "=f"(sb0), "=f"(sb1) : "l"(sb));

        int i0 = pq.x >> 5;
        atomicAdd(&out[(size_t)i0 * C_OUT + 2 * lane],     sa0);
        atomicAdd(&out[(size_t)i0 * C_OUT + 2 * lane + 1], sa1);
        if (has1) {
            int i1 = pq.z >> 5;
            atomicAdd(&out[(size_t)i1 * C_OUT + 2 * lane],     sb0);
            atomicAdd(&out[(size_t)i1 * C_OUT + 2 * lane + 1], sb1);
        }
    }
}

extern "C" void kernel_launch(void* const* d_in, const int* in_sizes, int n_in,
                              void* d_out, int out_size) {
    const float* feat = (const float*)d_in[0];
    const int*   idx  = (const int*)d_in[1];
    const float* w    = (const float*)d_in[2];
    float* out = (float*)d_out;

    int n = in_sizes[0] / C_IN;
    int ntiles = (n + TILE - 1) / TILE;

    // Fork: center (independent of grid/bitmap) on the side stream,
    // concurrent with the clear -> scatter -> probe chain. Non-persistent
    // center blocks retire quickly, letting chain blocks interleave.
    cudaEventRecord(g_ev_fork, 0);
    cudaStreamWaitEvent(g_s1, g_ev_fork, 0);
    center_kernel<<<ntiles, 256, 0, g_s1>>>(feat, w, out, n);
    cudaEventRecord(g_ev_join, g_s1);

    clear_bitmap_kernel<<<(NWORDS / 4 + 255) / 256, 256>>>();
    scatter_kernel<<<(n + 255) / 256, 256>>>(idx, n);
    probe_kernel<<<(n + 255) / 256, 256>>>(idx, n);

    // Join: pairs needs both probe's pair list and center's stores.
    cudaStreamWaitEvent(0, g_ev_join, 0);
    pairs_kernel<<<1184, 128>>>(feat, w, out);
}

// round 14
// speedup vs baseline: 1.2676x; 1.2676x over previous
#include <cuda_runtime.h>
#include <cstdint>

#define Zdim 41
#define Ydim 1024
#define Xdim 1024
#define NVOX (Zdim * Ydim * Xdim)      // 42,991,616
#define NWORDS (NVOX / 32)             // 1,343,488
#define C_IN 32
#define C_OUT 64
#define KVOL 27
#define KCENTER 13
#define MAXN 300000
#define TILE 64

// Dense index grid: validity gated by g_bitmap (wiped each launch); the grid
// itself is never cleared, so stale entries are never read.
__device__ int      g_grid[NVOX];
__device__ unsigned g_bitmap[NWORDS];
__device__ int      g_npairs;
__device__ int2     g_pairs[MAXN * 8];

// Side stream (lowest priority: chain blocks win free SM slots) + fork/join
// events, created once at static init. Host-side driver resources only.
static cudaStream_t g_s1;
static cudaEvent_t  g_ev_fork, g_ev_join;
namespace {
struct StreamInit {
    StreamInit() {
        int leastP = 0, greatestP = 0;
        cudaDeviceGetStreamPriorityRange(&leastP, &greatestP);
        cudaStreamCreateWithPriority(&g_s1, cudaStreamNonBlocking, leastP);
        cudaEventCreateWithFlags(&g_ev_fork, cudaEventDisableTiming);
        cudaEventCreateWithFlags(&g_ev_join, cudaEventDisableTiming);
    }
};
StreamInit g_stream_init;
}

__global__ void clear_bitmap_kernel() {
    int i = blockIdx.x * blockDim.x + threadIdx.x;
    if (i == 0) g_npairs = 0;
    if (i * 4 < NWORDS) ((uint4*)g_bitmap)[i] = make_uint4(0, 0, 0, 0);
}

__global__ void scatter_kernel(const int* __restrict__ idx, int n) {
    int i = blockIdx.x * blockDim.x + threadIdx.x;
    if (i >= n) return;
    int4 v = ((const int4*)idx)[i];
    unsigned lin = (unsigned)v.y * (Ydim * Xdim) + (unsigned)v.z * Xdim + (unsigned)v.w;
    g_grid[lin] = i;
    atomicOr(&g_bitmap[lin >> 5], 1u << (lin & 31));
}

// Symmetric probing (R12 group form: thread = (point, group), 5 groups cover
// the 13 k<13 offsets; each hit emits pair + mirror). Pair emission is
// WARP-AGGREGATED: per-lane hit buffer, shfl prefix scan, ONE atomicAdd per
// warp -- the per-hit same-address atomic was the measured bottleneck.
__global__ void probe_kernel(const int* __restrict__ idx, int n) {
    int t = blockIdx.x * blockDim.x + threadIdx.x;
    int lane = threadIdx.x & 31;
    bool valid = t < n * 5;

    int kk[3];
    int nbv[3];
    int cnt = 0;
    int i = 0;

    if (valid) {
        i = t / 5;
        int g = t - i * 5;
        int4 v = ((const int4*)idx)[i];

        int dz = (g < 3) ? -1 : 0;       // groups: (-1,-1) (-1,0) (-1,1) (0,-1) (0,0)
        int dy = (g < 3) ? (g - 1) : (g - 4);
        int nz = v.y + dz;
        int ny = v.z + dy;
        if ((unsigned)nz < Zdim && (unsigned)ny < Ydim) {
            unsigned rowbase = ((unsigned)nz * Ydim + (unsigned)ny) * Xdim;
            int x = v.w;
            unsigned lin0 = rowbase + (unsigned)x;
            unsigned w0   = g_bitmap[lin0 >> 5];

            int kbase = (dz + 1) * 9 + (dy + 1) * 3;
            int dxhi = (g == 4) ? -1 : 1;

            #pragma unroll
            for (int dx = -1; dx <= 1; ++dx) {
                if (dx > dxhi) break;
                int nx = x + dx;
                if ((unsigned)nx >= Xdim) continue;
                unsigned lin = rowbase + (unsigned)nx;
                unsigned word = ((lin >> 5) == (lin0 >> 5)) ? w0 : g_bitmap[lin >> 5];
                if ((word >> (lin & 31)) & 1u) {
                    kk[cnt]  = kbase + dx + 1;
                    nbv[cnt] = g_grid[lin];          // rare
                    ++cnt;
                }
            }
        }
    }

    // warp-aggregated emission: inclusive shfl scan of per-lane counts
    unsigned pre = (unsigned)cnt;
    #pragma unroll
    for (int d = 1; d < 32; d <<= 1) {
        unsigned v = __shfl_up_sync(0xffffffffu, pre, d);
        if (lane >= d) pre += v;
    }
    unsigned warptotal = __shfl_sync(0xffffffffu, pre, 31);
    unsigned excl = pre - (unsigned)cnt;

    unsigned base = 0;
    if (lane == 31 && warptotal)
        base = atomicAdd(&g_npairs, 2 * (int)warptotal);
    base = __shfl_sync(0xffffffffu, base, 31);

    for (int j = 0; j < cnt; ++j) {
        int pos = (int)base + 2 * ((int)excl + j);
        int k  = kk[j];
        int nb = nbv[j];
        g_pairs[pos]     = make_int2((i  << 5) | k,        nb);
        g_pairs[pos + 1] = make_int2((nb << 5) | (26 - k), i);
    }
}

__device__ __forceinline__ void fma2(unsigned long long& acc, float f,
                                     unsigned long long wv) {
    unsigned long long fv2;
    asm("mov.b64 %0, {%1, %1};" : "=l"(fv2) : "f"(f));
    asm("fma.rn.f32x2 %0, %1, %2, %3;" : "=l"(acc) : "l"(fv2), "l"(wv), "l"(acc));
}

// Center matvec, software-pipelined persistent form (R10/R12 proven).
// Lane owns couts (2*lane, 2*lane+1): packed u64 weights in registers,
// broadcast LDS.128 features, one STG.64 per point.
__global__ void __launch_bounds__(256) center_kernel(
    const float* __restrict__ feat, const float* __restrict__ w,
    float* __restrict__ out, int n)
{
    __shared__ float4 sf[2][TILE * (C_IN / 4)];

    int tid   = threadIdx.x;
    int lane  = tid & 31;
    int wslot = tid >> 5;

    const float* w13 = w + KCENTER * C_IN * C_OUT;
    unsigned long long wreg[C_IN];
    #pragma unroll
    for (int c = 0; c < C_IN; ++c)
        wreg[c] = ((const unsigned long long*)w13)[c * 32 + lane];

    const float4* featv = (const float4*)feat;
    long maxf4 = (long)n * (C_IN / 4) - 1;
    int ntiles = (n + TILE - 1) / TILE;

    int t = blockIdx.x;
    float4 r0, r1;
    if (t < ntiles) {
        long base = (long)t * (TILE * C_IN / 4);
        long i0 = base + tid;       if (i0 > maxf4) i0 = maxf4;
        long i1 = base + tid + 256; if (i1 > maxf4) i1 = maxf4;
        r0 = featv[i0];
        r1 = featv[i1];
    }

    int buf = 0;
    for (; t < ntiles; t += gridDim.x) {
        sf[buf][tid]       = r0;
        sf[buf][tid + 256] = r1;
        __syncthreads();

        int tn = t + gridDim.x;
        if (tn < ntiles) {
            long base = (long)tn * (TILE * C_IN / 4);
            long i0 = base + tid;       if (i0 > maxf4) i0 = maxf4;
            long i1 = base + tid + 256; if (i1 > maxf4) i1 = maxf4;
            r0 = featv[i0];
            r1 = featv[i1];
        }

        int p0 = wslot * 8;
        #pragma unroll
        for (int pp = 0; pp < 8; ++pp) {
            int i = t * TILE + p0 + pp;
            if (i >= n) break;
            const float4* frow = &sf[buf][(p0 + pp) * (C_IN / 4)];
            unsigned long long acc0, acc1, acc2, acc3;
            asm("mov.b64 %0, {%1, %1};" : "=l"(acc0) : "f"(0.0f));
            asm("mov.b64 %0, {%1, %1};" : "=l"(acc1) : "f"(0.0f));
            asm("mov.b64 %0, {%1, %1};" : "=l"(acc2) : "f"(0.0f));
            asm("mov.b64 %0, {%1, %1};" : "=l"(acc3) : "f"(0.0f));
            #pragma unroll
            for (int c4 = 0; c4 < C_IN / 4; ++c4) {
                float4 fv = frow[c4];                // broadcast LDS.128
                fma2(acc0, fv.x, wreg[c4 * 4 + 0]);
                fma2(acc1, fv.y, wreg[c4 * 4 + 1]);
                fma2(acc2, fv.z, wreg[c4 * 4 + 2]);
                fma2(acc3, fv.w, wreg[c4 * 4 + 3]);
            }
            unsigned long long s01, s23, s;
            asm("add.rn.f32x2 %0, %1, %2;" : "=l"(s01) : "l"(acc0), "l"(acc1));
            asm("add.rn.f32x2 %0, %1, %2;" : "=l"(s23) : "l"(acc2), "l"(acc3));
            asm("add.rn.f32x2 %0, %1, %2;" : "=l"(s)   : "l"(s01),  "l"(s23));
            ((unsigned long long*)out)[(size_t)i * 32 + lane] = s;   // STG.64
        }
        __syncthreads();
        buf ^= 1;
    }
}

// Rare neighbor contributions. 2 pairs/warp-iteration; ALL 16 feature
// float4 loads preloaded into registers before any FMA (MLP=16).
// Weights packed u64 (lane owns couts 2lane/2lane+1), hot in L1/L2.
__global__ void __launch_bounds__(128, 4) pairs_kernel(
    const float* __restrict__ feat,
    const float* __restrict__ w,
    float* __restrict__ out)
{
    int lane   = threadIdx.x & 31;
    int warp_g = (blockIdx.x * blockDim.x + threadIdx.x) >> 5;
    int nwarps = (gridDim.x * blockDim.x) >> 5;
    int np = g_npairs;

    for (int p = warp_g * 2; p < np; p += nwarps * 2) {
        int4 pq = ((const int4*)g_pairs)[p >> 1];
        bool has1 = (p + 1) < np;

        const float4* f0v = (const float4*)(feat + (size_t)pq.y * C_IN);
        const float4* f1v = (const float4*)(feat + (size_t)(has1 ? pq.w : pq.y) * C_IN);

        float4 f0[8], f1[8];
        #pragma unroll
        for (int c4 = 0; c4 < 8; ++c4) f0[c4] = f0v[c4];
        #pragma unroll
        for (int c4 = 0; c4 < 8; ++c4) f1[c4] = f1v[c4];

        const unsigned long long* wk0 =
            (const unsigned long long*)(w + (size_t)(pq.x & 31) * C_IN * C_OUT);
        const unsigned long long* wk1 =
            (const unsigned long long*)(w + (size_t)(pq.z & 31) * C_IN * C_OUT);

        unsigned long long a0, a1, b0, b1;
        asm("mov.b64 %0, {%1, %1};" : "=l"(a0) : "f"(0.0f));
        asm("mov.b64 %0, {%1, %1};" : "=l"(a1) : "f"(0.0f));
        asm("mov.b64 %0, {%1, %1};" : "=l"(b0) : "f"(0.0f));
        asm("mov.b64 %0, {%1, %1};" : "=l"(b1) : "f"(0.0f));

        #pragma unroll
        for (int c4 = 0; c4 < 8; ++c4) {
            fma2(a0, f0[c4].x, wk0[(c4 * 4 + 0) * 32 + lane]);
            fma2(a1, f0[c4].y, wk0[(c4 * 4 + 1) * 32 + lane]);
            fma2(a0, f0[c4].z, wk0[(c4 * 4 + 2) * 32 + lane]);
            fma2(a1, f0[c4].w, wk0[(c4 * 4 + 3) * 32 + lane]);
            fma2(b0, f1[c4].x, wk1[(c4 * 4 + 0) * 32 + lane]);
            fma2(b1, f1[c4].y, wk1[(c4 * 4 + 1) * 32 + lane]);
            fma2(b0, f1[c4].z, wk1[(c4 * 4 + 2) * 32 + lane]);
            fma2(b1, f1[c4].w, wk1[(c4 * 4 + 3) * 32 + lane]);
        }

        unsigned long long sa, sb;
        asm("add.rn.f32x2 %0, %1, %2;" : "=l"(sa) : "l"(a0), "l"(a1));
        asm("add.rn.f32x2 %0, %1, %2;" : "=l"(sb) : "l"(b0), "l"(b1));
        float sa0, sa1, sb0, sb1;
        asm("mov.b64 {%0, %1}, %2;" : "=f"(sa0), "=f"(sa1) : "l"(sa));
        asm("mov.b64 {%0, %1}, %2;" : "=f"(sb0), "=f"(sb1) : "l"(sb));

        int i0 = pq.x >> 5;
        atomicAdd(&out[(size_t)i0 * C_OUT + 2 * lane],     sa0);
        atomicAdd(&out[(size_t)i0 * C_OUT + 2 * lane + 1], sa1);
        if (has1) {
            int i1 = pq.z >> 5;
            atomicAdd(&out[(size_t)i1 * C_OUT + 2 * lane],     sb0);
            atomicAdd(&out[(size_t)i1 * C_OUT + 2 * lane + 1], sb1);
        }
    }
}

extern "C" void kernel_launch(void* const* d_in, const int* in_sizes, int n_in,
                              void* d_out, int out_size) {
    const float* feat = (const float*)d_in[0];
    const int*   idx  = (const int*)d_in[1];
    const float* w    = (const float*)d_in[2];
    float* out = (float*)d_out;

    int n = in_sizes[0] / C_IN;

    // Fork: center (independent of grid/bitmap) on the low-priority side
    // stream, concurrent with the clear -> scatter -> probe chain.
    cudaEventRecord(g_ev_fork, 0);
    cudaStreamWaitEvent(g_s1, g_ev_fork, 0);
    center_kernel<<<296, 256, 0, g_s1>>>(feat, w, out, n);
    cudaEventRecord(g_ev_join, g_s1);

    clear_bitmap_kernel<<<(NWORDS / 4 + 255) / 256, 256>>>();
    scatter_kernel<<<(n + 255) / 256, 256>>>(idx, n);
    probe_kernel<<<(n * 5 + 255) / 256, 256>>>(idx, n);

    // Join: pairs needs both probe's pair list and center's stores.
    cudaStreamWaitEvent(0, g_ev_join, 0);
    pairs_kernel<<<1184, 128>>>(feat, w, out);
}

// round 15
// speedup vs baseline: 1.3596x; 1.0726x over previous
#include <cuda_runtime.h>
#include <cstdint>

#define Zdim 41
#define Ydim 1024
#define Xdim 1024
#define NVOX (Zdim * Ydim * Xdim)      // 42,991,616
#define NWORDS (NVOX / 32)             // 1,343,488
#define C_IN 32
#define C_OUT 64
#define KVOL 27
#define KCENTER 13
#define MAXN 300000
#define TILE 64

// Dense index grid: validity gated by g_bitmap (wiped each launch); the grid
// itself is never cleared, so stale entries are never read.
__device__ int      g_grid[NVOX];
__device__ unsigned g_bitmap[NWORDS];
__device__ int      g_npairs;
__device__ int2     g_pairs[MAXN * 8];

// Side stream at HIGHEST priority: center's 148 blocks must land 1-per-SM
// immediately (half the RF each), so chain blocks co-reside in the other
// half and run inside center's idle issue slots. Static-init host resources.
static cudaStream_t g_s1;
static cudaEvent_t  g_ev_fork, g_ev_join;
namespace {
struct StreamInit {
    StreamInit() {
        int leastP = 0, greatestP = 0;
        cudaDeviceGetStreamPriorityRange(&leastP, &greatestP);
        cudaStreamCreateWithPriority(&g_s1, cudaStreamNonBlocking, greatestP);
        cudaEventCreateWithFlags(&g_ev_fork, cudaEventDisableTiming);
        cudaEventCreateWithFlags(&g_ev_join, cudaEventDisableTiming);
    }
};
StreamInit g_stream_init;
}

__global__ void clear_bitmap_kernel() {
    int i = blockIdx.x * blockDim.x + threadIdx.x;
    if (i == 0) g_npairs = 0;
    if (i * 4 < NWORDS) ((uint4*)g_bitmap)[i] = make_uint4(0, 0, 0, 0);
}

__global__ void scatter_kernel(const int* __restrict__ idx, int n) {
    int i = blockIdx.x * blockDim.x + threadIdx.x;
    if (i >= n) return;
    int4 v = ((const int4*)idx)[i];
    unsigned lin = (unsigned)v.y * (Ydim * Xdim) + (unsigned)v.z * Xdim + (unsigned)v.w;
    g_grid[lin] = i;
    atomicOr(&g_bitmap[lin >> 5], 1u << (lin & 31));
}

// Symmetric probing (thread = (point, group); 5 groups cover the 13 k<13
// offsets; each hit emits pair + mirror). Warp-aggregated emission.
__global__ void probe_kernel(const int* __restrict__ idx, int n) {
    int t = blockIdx.x * blockDim.x + threadIdx.x;
    int lane = threadIdx.x & 31;
    bool valid = t < n * 5;

    int kk[3];
    int nbv[3];
    int cnt = 0;
    int i = 0;

    if (valid) {
        i = t / 5;
        int g = t - i * 5;
        int4 v = ((const int4*)idx)[i];

        int dz = (g < 3) ? -1 : 0;       // groups: (-1,-1) (-1,0) (-1,1) (0,-1) (0,0)
        int dy = (g < 3) ? (g - 1) : (g - 4);
        int nz = v.y + dz;
        int ny = v.z + dy;
        if ((unsigned)nz < Zdim && (unsigned)ny < Ydim) {
            unsigned rowbase = ((unsigned)nz * Ydim + (unsigned)ny) * Xdim;
            int x = v.w;
            unsigned lin0 = rowbase + (unsigned)x;
            unsigned w0   = g_bitmap[lin0 >> 5];

            int kbase = (dz + 1) * 9 + (dy + 1) * 3;
            int dxhi = (g == 4) ? -1 : 1;

            #pragma unroll
            for (int dx = -1; dx <= 1; ++dx) {
                if (dx > dxhi) break;
                int nx = x + dx;
                if ((unsigned)nx >= Xdim) continue;
                unsigned lin = rowbase + (unsigned)nx;
                unsigned word = ((lin >> 5) == (lin0 >> 5)) ? w0 : g_bitmap[lin >> 5];
                if ((word >> (lin & 31)) & 1u) {
                    kk[cnt]  = kbase + dx + 1;
                    nbv[cnt] = g_grid[lin];          // rare
                    ++cnt;
                }
            }
        }
    }

    unsigned pre = (unsigned)cnt;
    #pragma unroll
    for (int d = 1; d < 32; d <<= 1) {
        unsigned v = __shfl_up_sync(0xffffffffu, pre, d);
        if (lane >= d) pre += v;
    }
    unsigned warptotal = __shfl_sync(0xffffffffu, pre, 31);
    unsigned excl = pre - (unsigned)cnt;

    unsigned base = 0;
    if (lane == 31 && warptotal)
        base = atomicAdd(&g_npairs, 2 * (int)warptotal);
    base = __shfl_sync(0xffffffffu, base, 31);

    for (int j = 0; j < cnt; ++j) {
        int pos = (int)base + 2 * ((int)excl + j);
        int k  = kk[j];
        int nb = nbv[j];
        g_pairs[pos]     = make_int2((i  << 5) | k,        nb);
        g_pairs[pos + 1] = make_int2((nb << 5) | (26 - k), i);
    }
}

__device__ __forceinline__ void fma2(unsigned long long& acc, float f,
                                     unsigned long long wv) {
    unsigned long long fv2;
    asm("mov.b64 %0, {%1, %1};" : "=l"(fv2) : "f"(f));
    asm("fma.rn.f32x2 %0, %1, %2, %3;" : "=l"(acc) : "l"(fv2), "l"(wv), "l"(acc));
}

// Center matvec, software-pipelined persistent form. ONE block per SM
// (grid=148): uses half the RF, leaving room for chain-kernel blocks to
// co-reside and consume the issue slots center leaves idle.
__global__ void __launch_bounds__(256) center_kernel(
    const float* __restrict__ feat, const float* __restrict__ w,
    float* __restrict__ out, int n)
{
    __shared__ float4 sf[2][TILE * (C_IN / 4)];

    int tid   = threadIdx.x;
    int lane  = tid & 31;
    int wslot = tid >> 5;

    const float* w13 = w + KCENTER * C_IN * C_OUT;
    unsigned long long wreg[C_IN];
    #pragma unroll
    for (int c = 0; c < C_IN; ++c)
        wreg[c] = ((const unsigned long long*)w13)[c * 32 + lane];

    const float4* featv = (const float4*)feat;
    long maxf4 = (long)n * (C_IN / 4) - 1;
    int ntiles = (n + TILE - 1) / TILE;

    int t = blockIdx.x;
    float4 r0, r1;
    if (t < ntiles) {
        long base = (long)t * (TILE * C_IN / 4);
        long i0 = base + tid;       if (i0 > maxf4) i0 = maxf4;
        long i1 = base + tid + 256; if (i1 > maxf4) i1 = maxf4;
        r0 = featv[i0];
        r1 = featv[i1];
    }

    int buf = 0;
    for (; t < ntiles; t += gridDim.x) {
        sf[buf][tid]       = r0;
        sf[buf][tid + 256] = r1;
        __syncthreads();

        int tn = t + gridDim.x;
        if (tn < ntiles) {
            long base = (long)tn * (TILE * C_IN / 4);
            long i0 = base + tid;       if (i0 > maxf4) i0 = maxf4;
            long i1 = base + tid + 256; if (i1 > maxf4) i1 = maxf4;
            r0 = featv[i0];
            r1 = featv[i1];
        }

        int p0 = wslot * 8;
        #pragma unroll
        for (int pp = 0; pp < 8; ++pp) {
            int i = t * TILE + p0 + pp;
            if (i >= n) break;
            const float4* frow = &sf[buf][(p0 + pp) * (C_IN / 4)];
            unsigned long long acc0, acc1, acc2, acc3;
            asm("mov.b64 %0, {%1, %1};" : "=l"(acc0) : "f"(0.0f));
            asm("mov.b64 %0, {%1, %1};" : "=l"(acc1) : "f"(0.0f));
            asm("mov.b64 %0, {%1, %1};" : "=l"(acc2) : "f"(0.0f));
            asm("mov.b64 %0, {%1, %1};" : "=l"(acc3) : "f"(0.0f));
            #pragma unroll
            for (int c4 = 0; c4 < C_IN / 4; ++c4) {
                float4 fv = frow[c4];                // broadcast LDS.128
                fma2(acc0, fv.x, wreg[c4 * 4 + 0]);
                fma2(acc1, fv.y, wreg[c4 * 4 + 1]);
                fma2(acc2, fv.z, wreg[c4 * 4 + 2]);
                fma2(acc3, fv.w, wreg[c4 * 4 + 3]);
            }
            unsigned long long s01, s23, s;
            asm("add.rn.f32x2 %0, %1, %2;" : "=l"(s01) : "l"(acc0), "l"(acc1));
            asm("add.rn.f32x2 %0, %1, %2;" : "=l"(s23) : "l"(acc2), "l"(acc3));
            asm("add.rn.f32x2 %0, %1, %2;" : "=l"(s)   : "l"(s01),  "l"(s23));
            ((unsigned long long*)out)[(size_t)i * 32 + lane] = s;   // STG.64
        }
        __syncthreads();
        buf ^= 1;
    }
}

// Rare neighbor contributions. 2 pairs/warp-iteration; ALL 16 feature
// float4 loads preloaded into registers before any FMA (MLP=16).
__global__ void __launch_bounds__(128, 4) pairs_kernel(
    const float* __restrict__ feat,
    const float* __restrict__ w,
    float* __restrict__ out)
{
    int lane   = threadIdx.x & 31;
    int warp_g = (blockIdx.x * blockDim.x + threadIdx.x) >> 5;
    int nwarps = (gridDim.x * blockDim.x) >> 5;
    int np = g_npairs;

    for (int p = warp_g * 2; p < np; p += nwarps * 2) {
        int4 pq = ((const int4*)g_pairs)[p >> 1];
        bool has1 = (p + 1) < np;

        const float4* f0v = (const float4*)(feat + (size_t)pq.y * C_IN);
        const float4* f1v = (const float4*)(feat + (size_t)(has1 ? pq.w : pq.y) * C_IN);

        float4 f0[8], f1[8];
        #pragma unroll
        for (int c4 = 0; c4 < 8; ++c4) f0[c4] = f0v[c4];
        #pragma unroll
        for (int c4 = 0; c4 < 8; ++c4) f1[c4] = f1v[c4];

        const unsigned long long* wk0 =
            (const unsigned long long*)(w + (size_t)(pq.x & 31) * C_IN * C_OUT);
        const unsigned long long* wk1 =
            (const unsigned long long*)(w + (size_t)(pq.z & 31) * C_IN * C_OUT);

        unsigned long long a0, a1, b0, b1;
        asm("mov.b64 %0, {%1, %1};" : "=l"(a0) : "f"(0.0f));
        asm("mov.b64 %0, {%1, %1};" : "=l"(a1) : "f"(0.0f));
        asm("mov.b64 %0, {%1, %1};" : "=l"(b0) : "f"(0.0f));
        asm("mov.b64 %0, {%1, %1};" : "=l"(b1) : "f"(0.0f));

        #pragma unroll
        for (int c4 = 0; c4 < 8; ++c4) {
            fma2(a0, f0[c4].x, wk0[(c4 * 4 + 0) * 32 + lane]);
            fma2(a1, f0[c4].y, wk0[(c4 * 4 + 1) * 32 + lane]);
            fma2(a0, f0[c4].z, wk0[(c4 * 4 + 2) * 32 + lane]);
            fma2(a1, f0[c4].w, wk0[(c4 * 4 + 3) * 32 + lane]);
            fma2(b0, f1[c4].x, wk1[(c4 * 4 + 0) * 32 + lane]);
            fma2(b1, f1[c4].y, wk1[(c4 * 4 + 1) * 32 + lane]);
            fma2(b0, f1[c4].z, wk1[(c4 * 4 + 2) * 32 + lane]);
            fma2(b1, f1[c4].w, wk1[(c4 * 4 + 3) * 32 + lane]);
        }

        unsigned long long sa, sb;
        asm("add.rn.f32x2 %0, %1, %2;" : "=l"(sa) : "l"(a0), "l"(a1));
        asm("add.rn.f32x2 %0, %1, %2;" : "=l"(sb) : "l"(b0), "l"(b1));
        float sa0, sa1, sb0, sb1;
        asm("mov.b64 {%0, %1}, %2;" : "=f"(sa0), "=f"(sa1) : "l"(sa));
        asm("mov.b64 {%0, %1}, %2;" : "=f"(sb0), "=f"(sb1) : "l"(sb));

        int i0 = pq.x >> 5;
        atomicAdd(&out[(size_t)i0 * C_OUT + 2 * lane],     sa0);
        atomicAdd(&out[(size_t)i0 * C_OUT + 2 * lane + 1], sa1);
        if (has1) {
            int i1 = pq.z >> 5;
            atomicAdd(&out[(size_t)i1 * C_OUT + 2 * lane],     sb0);
            atomicAdd(&out[(size_t)i1 * C_OUT + 2 * lane + 1], sb1);
        }
    }
}

extern "C" void kernel_launch(void* const* d_in, const int* in_sizes, int n_in,
                              void* d_out, int out_size) {
    const float* feat = (const float*)d_in[0];
    const int*   idx  = (const int*)d_in[1];
    const float* w    = (const float*)d_in[2];
    float* out = (float*)d_out;

    int n = in_sizes[0] / C_IN;

    // Fork: center on high-priority side stream, ONE block per SM so chain
    // blocks co-reside in the remaining half of each SM's register file.
    cudaEventRecord(g_ev_fork, 0);
    cudaStreamWaitEvent(g_s1, g_ev_fork, 0);
    center_kernel<<<148, 256, 0, g_s1>>>(feat, w, out, n);
    cudaEventRecord(g_ev_join, g_s1);

    clear_bitmap_kernel<<<(NWORDS / 4 + 255) / 256, 256>>>();
    scatter_kernel<<<(n + 255) / 256, 256>>>(idx, n);
    probe_kernel<<<(n * 5 + 255) / 256, 256>>>(idx, n);

    // Join: pairs needs both probe's pair list and center's stores.
    cudaStreamWaitEvent(0, g_ev_join, 0);
    pairs_kernel<<<1184, 128>>>(feat, w, out);
}